// round 12
// baseline (speedup 1.0000x reference)
#include <cuda_runtime.h>

#define BATCH 256

typedef unsigned long long ull;

// ---------------- device scratch (no allocations allowed) ----------------
// pair-duplicated weights: [o][c][g][10 pairs] = 20 floats (9 taps + pad)
__device__ __align__(16) float g_W1[8  * 3  * 7 * 20];   // 3360
__device__ __align__(16) float g_W2[16 * 8  * 7 * 20];   // 17920
__device__ __align__(16) float g_W3[32 * 16 * 7 * 20];   // 71680
__device__ float g_out1[BATCH * 8  * 16 * 16];
__device__ float g_out2[BATCH * 16 * 8 * 8];
__device__ float g_out3[BATCH * 32 * 4 * 4];

// ---------------- packed f32x2 helpers ----------------
__device__ __forceinline__ void ffma2(ull& acc, ull a, ull b) {
    asm("fma.rn.f32x2 %0, %1, %2, %0;" : "+l"(acc) : "l"(a), "l"(b));
}
__device__ __forceinline__ ull pk_mid(ull A, ull B) {
    // (A.hi, B.lo) — half-extracts are register naming; one reg-pair build
    unsigned a0, a1, b0, b1;
    asm("mov.b64 {%0,%1}, %2;" : "=r"(a0), "=r"(a1) : "l"(A));
    asm("mov.b64 {%0,%1}, %2;" : "=r"(b0), "=r"(b1) : "l"(B));
    ull M;
    asm("mov.b64 %0, {%1,%2};" : "=l"(M) : "r"(a1), "r"(b0));
    return M;
}
__device__ __forceinline__ void upk(ull v, float& lo, float& hi) {
    asm("mov.b64 {%0,%1}, %2;" : "=f"(lo), "=f"(hi) : "l"(v));
}

// ---------------- spline/silu feature expansion ----------------
__device__ __forceinline__ void compute_phi(float v, float* phi) {
    const float h = 2.0f / 3.0f;
    float b[9];
#pragma unroll
    for (int i = 0; i < 9; i++) {
        float t0 = (i - 3) * h - 1.0f;
        float t1 = (i - 2) * h - 1.0f;
        b[i] = (v >= t0 && v < t1) ? 1.0f : 0.0f;
    }
#pragma unroll
    for (int j = 1; j <= 3; j++) {
        float inv = 1.0f / (j * h);
#pragma unroll
        for (int i = 0; i + j < 9; i++) {
            float ti  = (i - 3) * h - 1.0f;
            float tj1 = (i + j - 2) * h - 1.0f;
            b[i] = (v - ti) * inv * b[i] + (tj1 - v) * inv * b[i + 1];
        }
    }
    phi[0] = v / (1.0f + __expf(-v));
#pragma unroll
    for (int g = 0; g < 6; g++) phi[g + 1] = b[g];
}

// ---------------- prep: fold scaler, duplicate into pairs ----------------
template <int O, int C>
__device__ __forceinline__ void fold_w(float* Wd, int i, const float* __restrict__ bw,
                                       const float* __restrict__ sw, const float* __restrict__ sc) {
    int p = i % 10;
    int g = (i / 10) % 7;
    int c = (i / 70) % C;
    int o = i / (70 * C);
    float val = 0.0f;
    if (p < 9) {
        int f = c * 9 + p;
        constexpr int F = C * 9;
        val = (g == 0) ? bw[o * F + f] : sw[(o * F + f) * 6 + (g - 1)] * sc[o * F + f];
    }
    Wd[i * 2]     = val;
    Wd[i * 2 + 1] = val;
}

#define NP1 (8 * 3 * 7 * 10)
#define NP2 (16 * 8 * 7 * 10)
#define NP3 (32 * 16 * 7 * 10)
#define NPREP (NP1 + NP2 + NP3)

__global__ void prep_all(
    const float* __restrict__ c1bw, const float* __restrict__ c1sw, const float* __restrict__ c1sc,
    const float* __restrict__ c2bw, const float* __restrict__ c2sw, const float* __restrict__ c2sc,
    const float* __restrict__ c3bw, const float* __restrict__ c3sw, const float* __restrict__ c3sc)
{
    int i = blockIdx.x * blockDim.x + threadIdx.x;
    if (i < NP1) {
        fold_w<8, 3>(g_W1, i, c1bw, c1sw, c1sc);
    } else if (i < NP1 + NP2) {
        fold_w<16, 8>(g_W2, i - NP1, c2bw, c2sw, c2sc);
    } else if (i < NPREP) {
        fold_w<32, 16>(g_W3, i - NP1 - NP2, c3bw, c3sw, c3sc);
    }
}

// ---------------- vertically-paired FFMA2 conv inner loop ----------------
// E layout: [c][g][x][y], y stride 1, col stride YP=6 (SR=2 everywhere).
// acc[o][xoff] = f32x2 (conv[y0][x], conv[y1][x]); xoff in {0,1} = pool cols.
template <int CT, int OT, int Xd>
__device__ __forceinline__ void conv_body2(
    const float* E, const float* __restrict__ Wg, ull acc[OT][2],
    int c0, int pr, int px, int og_base, int C_total)
{
    const int y0 = 2 * pr;
#pragma unroll 1
    for (int cc = 0; cc < CT; cc++) {
        int c = c0 + cc;
#pragma unroll
        for (int g = 0; g < 7; g++) {
            ull P[3][4];
#pragma unroll
            for (int j = 0; j < 4; j++) {
                const float* col = &E[((c * 7 + g) * Xd + 2 * px + j) * 6 + y0];
                ull A = *reinterpret_cast<const ull*>(col);       // (y0, y1)
                ull B = *reinterpret_cast<const ull*>(col + 2);   // (y2, y3)
                P[0][j] = A;
                P[2][j] = B;
                P[1][j] = pk_mid(A, B);                           // (y1, y2)
            }
#pragma unroll
            for (int o = 0; o < OT; o++) {
                const ulonglong2* wv = reinterpret_cast<const ulonglong2*>(
                    &Wg[((og_base + o * C_total + c) * 7 + g) * 20]);
                ulonglong2 q0 = __ldg(wv + 0);
                ulonglong2 q1 = __ldg(wv + 1);
                ulonglong2 q2 = __ldg(wv + 2);
                ulonglong2 q3 = __ldg(wv + 3);
                ull w8 = __ldg(reinterpret_cast<const ull*>(wv + 4));
                ull w[9] = {q0.x, q0.y, q1.x, q1.y, q2.x, q2.y, q3.x, q3.y, w8};
                ull a0 = acc[o][0], a1 = acc[o][1];
#pragma unroll
                for (int kh = 0; kh < 3; kh++)
#pragma unroll
                    for (int kw = 0; kw < 3; kw++) {
                        ffma2(a0, P[kh][kw],     w[kh * 3 + kw]);
                        ffma2(a1, P[kh][kw + 1], w[kh * 3 + kw]);
                    }
                acc[o][0] = a0; acc[o][1] = a1;
            }
        }
    }
}

// ---------------- phi expansion of a strip into smem (y-innermost layout) ----------------
template <int C, int H, int W, int THREADS>
__device__ __forceinline__ void expand_strip(
    const float* __restrict__ inb, float* E, int s, int tid)
{
    constexpr int Yd = 6, Xd = W + 2;   // SR=2
    const int gy0 = 4 * s - 1;
    for (int i = tid; i < C * Yd * Xd; i += THREADS) {
        int x  = i % Xd;
        int ly = (i / Xd) % Yd;
        int c  = i / (Xd * Yd);
        int gy = gy0 + ly;
        float v = 0.0f;
        if (gy >= 0 && gy < H && x >= 1 && x <= W) v = __ldg(&inb[(c * H + gy) * W + x - 1]);
        float phi[7];
        compute_phi(v, phi);
#pragma unroll
        for (int g = 0; g < 7; g++) E[((c * 7 + g) * Xd + x) * 6 + ly] = phi[g];
    }
}

// ---------------- layers 1/2: strip kernel, 64 threads, SR=2 ----------------
template <int C, int H, int W, int O, int OT>
__global__ void __launch_bounds__(64, 8) kan_layer(
    const float* __restrict__ in, float* __restrict__ out, const float* __restrict__ Wg)
{
    constexpr int PW = W / 2, PH = H / 2;
    constexpr int OG = O / OT;
    constexpr int STRIPS = PH / 2;
    constexpr int Xd = W + 2;
    constexpr int THREADS = PW * 2 * OG;
    static_assert(THREADS == 64, "block must be 64 threads");

    extern __shared__ float E[];

    const int b   = blockIdx.x / STRIPS;
    const int s   = blockIdx.x % STRIPS;
    const int tid = threadIdx.x;

    expand_strip<C, H, W, THREADS>(in + (size_t)b * C * H * W, E, s, tid);
    __syncthreads();

    const int px = tid % PW;
    const int pr = (tid / PW) % 2;
    const int og = tid / (PW * 2);

    ull acc[OT][2];
#pragma unroll
    for (int o = 0; o < OT; o++) { acc[o][0] = 0ULL; acc[o][1] = 0ULL; }

    conv_body2<C, OT, Xd>(E, Wg, acc, 0, pr, px, og * OT * C, C);

    float* outb = out + (size_t)b * O * PH * PW;
    const int prow = s * 2 + pr;
#pragma unroll
    for (int o = 0; o < OT; o++) {
        float c00, c10, c01, c11;
        upk(acc[o][0], c00, c10);
        upk(acc[o][1], c01, c11);
        float m = fmaxf(fmaxf(c00, c10), fmaxf(c01, c11));
        outb[((og * OT + o) * PH + prow) * PW + px] = m;
    }
}

// ---------------- layer 3: channel-split (CS=2), SR=2, 128 threads ----------------
__global__ void __launch_bounds__(128, 4) kan_layer3(
    const float* __restrict__ in, float* __restrict__ out, const float* __restrict__ Wg)
{
    constexpr int C = 16, H = 8, W = 8, O = 32, OT = 4;
    constexpr int PW = W / 2, PH = H / 2;
    constexpr int OG = O / OT;                 // 8
    constexpr int STRIPS = PH / 2;             // 2
    constexpr int Xd = W + 2;                  // 10
    constexpr int THREADS = 128;
    constexpr int HALF = 64;

    extern __shared__ float E[];               // 16*7*10*6 = 6720 floats

    const int b   = blockIdx.x / STRIPS;
    const int s   = blockIdx.x % STRIPS;
    const int tid = threadIdx.x;

    expand_strip<C, H, W, THREADS>(in + (size_t)b * C * H * W, E, s, tid);
    __syncthreads();

    const int px = tid % PW;
    const int pr = (tid / PW) % 2;
    const int og = (tid / (PW * 2)) % OG;
    const int cs = tid / (PW * 2 * OG);        // 0 or 1, owns 8 channels

    ull acc[OT][2];
#pragma unroll
    for (int o = 0; o < OT; o++) { acc[o][0] = 0ULL; acc[o][1] = 0ULL; }

    conv_body2<8, OT, Xd>(E, Wg, acc, cs * 8, pr, px, og * OT * C, C);

    float y[OT][4];
#pragma unroll
    for (int o = 0; o < OT; o++) {
        upk(acc[o][0], y[o][0], y[o][1]);
        upk(acc[o][1], y[o][2], y[o][3]);
    }

    __syncthreads();                            // all conv reads of E done
    float* P = E;                               // reuse arena: 64*17 floats
    const int slot = tid % HALF;                // same (px,pr,og) across halves
    if (cs == 1) {
#pragma unroll
        for (int o = 0; o < OT; o++)
#pragma unroll
            for (int k = 0; k < 4; k++) P[slot * 17 + o * 4 + k] = y[o][k];
    }
    __syncthreads();
    if (cs == 0) {
        float* outb = out + (size_t)b * O * PH * PW;
        const int prow = s * 2 + pr;
#pragma unroll
        for (int o = 0; o < OT; o++) {
            float v0 = y[o][0] + P[slot * 17 + o * 4 + 0];
            float v1 = y[o][1] + P[slot * 17 + o * 4 + 1];
            float v2 = y[o][2] + P[slot * 17 + o * 4 + 2];
            float v3 = y[o][3] + P[slot * 17 + o * 4 + 3];
            float m = fmaxf(fmaxf(v0, v1), fmaxf(v2, v3));
            outb[((og * OT + o) * PH + prow) * PW + px] = m;
        }
    }
}

// ---------------- final linear 512 -> 100 (direct linw rows, float4) ----------------
__global__ void __launch_bounds__(128) linear_k(const float* __restrict__ linw,
                                                const float* __restrict__ bias,
                                                float* __restrict__ out) {
    __shared__ float hs[512];
    int b = blockIdx.x;
    for (int i = threadIdx.x; i < 512; i += 128) hs[i] = g_out3[b * 512 + i];
    __syncthreads();
    int j = threadIdx.x;
    if (j < 100) {
        float a = __ldg(&bias[j]);
        const float4* wr = reinterpret_cast<const float4*>(linw + (size_t)j * 512);
        const float4* h4 = reinterpret_cast<const float4*>(hs);
#pragma unroll 8
        for (int f = 0; f < 128; f++) {
            float4 w = __ldg(&wr[f]);
            float4 hv = h4[f];
            a += w.x * hv.x + w.y * hv.y + w.z * hv.z + w.w * hv.w;
        }
        out[(size_t)b * 100 + j] = a;
    }
}

extern "C" void kernel_launch(void* const* d_in, const int* in_sizes, int n_in,
                              void* d_out, int out_size) {
    const float* x     = (const float*)d_in[0];
    const float* c1bw  = (const float*)d_in[1];
    const float* c1sw  = (const float*)d_in[2];
    const float* c1sc  = (const float*)d_in[3];
    const float* c2bw  = (const float*)d_in[4];
    const float* c2sw  = (const float*)d_in[5];
    const float* c2sc  = (const float*)d_in[6];
    const float* c3bw  = (const float*)d_in[7];
    const float* c3sw  = (const float*)d_in[8];
    const float* c3sc  = (const float*)d_in[9];
    const float* linw  = (const float*)d_in[10];
    const float* linb  = (const float*)d_in[11];
    float* out = (float*)d_out;

    static float *p_W1, *p_W2, *p_W3, *p_o1, *p_o2, *p_o3;
    static bool init = false;
    if (!init) {
        cudaGetSymbolAddress((void**)&p_W1, g_W1);
        cudaGetSymbolAddress((void**)&p_W2, g_W2);
        cudaGetSymbolAddress((void**)&p_W3, g_W3);
        cudaGetSymbolAddress((void**)&p_o1, g_out1);
        cudaGetSymbolAddress((void**)&p_o2, g_out2);
        cudaGetSymbolAddress((void**)&p_o3, g_out3);
        init = true;
    }

    prep_all<<<(NPREP + 255) / 256, 256>>>(c1bw, c1sw, c1sc, c2bw, c2sw, c2sc,
                                           c3bw, c3sw, c3sc);

    // L1: C=3 O=8  OT=4 -> 64 thr (16*2*2), 8 strips, grid 2048, smem 3*7*34*6*4 = 17136 B
    kan_layer<3, 32, 32, 8, 4><<<BATCH * 8, 64, 3 * 7 * 34 * 6 * 4>>>(x, p_o1, p_W1);
    // L2: C=8 O=16 OT=4 -> 64 thr (8*2*4), 4 strips, grid 1024, smem 8*7*18*6*4 = 24192 B
    kan_layer<8, 16, 16, 16, 4><<<BATCH * 4, 64, 8 * 7 * 18 * 6 * 4>>>(p_o1, p_o2, p_W2);
    // L3: C=16 O=32 OT=4 CS=2 -> 128 thr, 2 strips, grid 512, smem 16*7*10*6*4 = 26880 B
    kan_layer3<<<BATCH * 2, 128, 16 * 7 * 10 * 6 * 4>>>(p_o2, p_o3, p_W3);

    linear_k<<<BATCH, 128>>>(linw, linb, out);
}

// round 13
// speedup vs baseline: 1.3197x; 1.3197x over previous
#include <cuda_runtime.h>

#define BATCH 256
#define HALFB 128

// ---------------- device scratch (no allocations allowed) ----------------
__device__ float g_W1[8  * 3  * 7 * 12];   // 2016
__device__ float g_W2[16 * 8  * 7 * 12];   // 10752
__device__ float g_W3[32 * 16 * 7 * 12];   // 43008
__device__ float g_out1[BATCH * 8  * 16 * 16];
__device__ float g_out2[BATCH * 16 * 8 * 8];
__device__ float g_out3[BATCH * 32 * 4 * 4];

// ---------------- spline/silu feature expansion ----------------
__device__ __forceinline__ void compute_phi(float v, float* phi) {
    const float h = 2.0f / 3.0f;
    float b[9];
#pragma unroll
    for (int i = 0; i < 9; i++) {
        float t0 = (i - 3) * h - 1.0f;
        float t1 = (i - 2) * h - 1.0f;
        b[i] = (v >= t0 && v < t1) ? 1.0f : 0.0f;
    }
#pragma unroll
    for (int j = 1; j <= 3; j++) {
        float inv = 1.0f / (j * h);
#pragma unroll
        for (int i = 0; i + j < 9; i++) {
            float ti  = (i - 3) * h - 1.0f;
            float tj1 = (i + j - 2) * h - 1.0f;
            b[i] = (v - ti) * inv * b[i] + (tj1 - v) * inv * b[i + 1];
        }
    }
    phi[0] = v / (1.0f + __expf(-v));
#pragma unroll
    for (int g = 0; g < 6; g++) phi[g + 1] = b[g];
}

// ---------------- prep: fold scaler into [o][c][g][12] ----------------
template <int O, int C>
__device__ __forceinline__ void fold_w(float* Wd, int i, const float* __restrict__ bw,
                                       const float* __restrict__ sw, const float* __restrict__ sc) {
    int kp = i % 12;
    int g  = (i / 12) % 7;
    int c  = (i / 84) % C;
    int o  = i / (84 * C);
    float val = 0.0f;
    if (kp < 9) {
        int f = c * 9 + kp;
        constexpr int F = C * 9;
        val = (g == 0) ? bw[o * F + f] : sw[(o * F + f) * 6 + (g - 1)] * sc[o * F + f];
    }
    Wd[i] = val;
}

#define NPREP (2016 + 10752 + 43008)

__global__ void prep_all(
    const float* __restrict__ c1bw, const float* __restrict__ c1sw, const float* __restrict__ c1sc,
    const float* __restrict__ c2bw, const float* __restrict__ c2sw, const float* __restrict__ c2sc,
    const float* __restrict__ c3bw, const float* __restrict__ c3sw, const float* __restrict__ c3sc)
{
    int i = blockIdx.x * blockDim.x + threadIdx.x;
    if (i < 2016) {
        fold_w<8, 3>(g_W1, i, c1bw, c1sw, c1sc);
    } else if (i < 2016 + 10752) {
        fold_w<16, 8>(g_W2, i - 2016, c2bw, c2sw, c2sc);
    } else if (i < NPREP) {
        fold_w<32, 16>(g_W3, i - 12768, c3bw, c3sw, c3sc);
    }
}

// ---------------- generic conv inner loop over CT channels ----------------
template <int CT, int OT, int Yd, int Xd>
__device__ __forceinline__ void conv_body(
    const float* E, const float* __restrict__ Wg, float acc[OT][4],
    int c0, int pr, int px, int og_base, int C_total)
{
#pragma unroll 1
    for (int cc = 0; cc < CT; cc++) {
        int c = c0 + cc;
#pragma unroll
        for (int g = 0; g < 7; g++) {
            float e[4][4];
            const int base = ((c * Yd + 2 * pr) * 7 + g) * Xd + 2 * px;
#pragma unroll
            for (int dy = 0; dy < 4; dy++) {
                const float2* r = reinterpret_cast<const float2*>(&E[base + dy * 7 * Xd]);
                float2 a = r[0], b2 = r[1];
                e[dy][0] = a.x; e[dy][1] = a.y; e[dy][2] = b2.x; e[dy][3] = b2.y;
            }
#pragma unroll
            for (int o = 0; o < OT; o++) {
                const float4* wv = reinterpret_cast<const float4*>(
                    &Wg[(((og_base + o * C_total) + c) * 7 + g) * 12]);
                float4 w0 = __ldg(&wv[0]);
                float4 w1 = __ldg(&wv[1]);
                float4 w2 = __ldg(&wv[2]);
                float wk[9] = {w0.x, w0.y, w0.z, w0.w, w1.x, w1.y, w1.z, w1.w, w2.x};
#pragma unroll
                for (int kh = 0; kh < 3; kh++)
#pragma unroll
                    for (int kw = 0; kw < 3; kw++) {
                        float wgt = wk[kh * 3 + kw];
                        acc[o][0] += e[kh][kw] * wgt;
                        acc[o][1] += e[kh][kw + 1] * wgt;
                        acc[o][2] += e[kh + 1][kw] * wgt;
                        acc[o][3] += e[kh + 1][kw + 1] * wgt;
                    }
            }
        }
    }
}

// ---------------- phi expansion of a strip into smem ----------------
template <int C, int H, int W, int SR, int THREADS>
__device__ __forceinline__ void expand_strip(
    const float* __restrict__ inb, float* E, int s, int tid)
{
    constexpr int Yd = 2 * SR + 2, Xd = W + 2;
    const int gy0 = 2 * s * SR - 1;
    for (int i = tid; i < C * Yd * Xd; i += THREADS) {
        int x  = i % Xd;
        int ly = (i / Xd) % Yd;
        int c  = i / (Xd * Yd);
        int gy = gy0 + ly;
        float v = 0.0f;
        if (gy >= 0 && gy < H && x >= 1 && x <= W) v = __ldg(&inb[(c * H + gy) * W + x - 1]);
        float phi[7];
        compute_phi(v, phi);
#pragma unroll
        for (int g = 0; g < 7; g++) E[((c * Yd + ly) * 7 + g) * Xd + x] = phi[g];
    }
}

// ---------------- layers 1/2: strip kernel, 64 threads ----------------
template <int C, int H, int W, int O, int OT, int SR>
__global__ void __launch_bounds__(64, 8) kan_layer(
    const float* __restrict__ in, float* __restrict__ out, const float* __restrict__ Wg)
{
    constexpr int PW = W / 2, PH = H / 2;
    constexpr int OG = O / OT;
    constexpr int STRIPS = PH / SR;
    constexpr int Yd = 2 * SR + 2, Xd = W + 2;
    constexpr int THREADS = PW * SR * OG;
    static_assert(THREADS == 64, "block must be 64 threads");

    extern __shared__ float E[];

    const int b   = blockIdx.x / STRIPS;
    const int s   = blockIdx.x % STRIPS;
    const int tid = threadIdx.x;

    expand_strip<C, H, W, SR, THREADS>(in + (size_t)b * C * H * W, E, s, tid);
    __syncthreads();

    const int px = tid % PW;
    const int pr = (tid / PW) % SR;
    const int og = tid / (PW * SR);

    float acc[OT][4];
#pragma unroll
    for (int o = 0; o < OT; o++) acc[o][0] = acc[o][1] = acc[o][2] = acc[o][3] = 0.0f;

    conv_body<C, OT, Yd, Xd>(E, Wg, acc, 0, pr, px, og * OT * C, C);

    float* outb = out + (size_t)b * O * PH * PW;
    const int prow = s * SR + pr;
#pragma unroll
    for (int o = 0; o < OT; o++) {
        float m = fmaxf(fmaxf(acc[o][0], acc[o][1]), fmaxf(acc[o][2], acc[o][3]));
        outb[((og * OT + o) * PH + prow) * PW + px] = m;
    }
}

// ---------------- layer 3: channel-split (CS=2), 128 threads ----------------
__global__ void __launch_bounds__(128, 4) kan_layer3(
    const float* __restrict__ in, float* __restrict__ out, const float* __restrict__ Wg)
{
    constexpr int C = 16, H = 8, W = 8, O = 32, OT = 4, SR = 2;
    constexpr int PW = W / 2, PH = H / 2;
    constexpr int OG = O / OT;                 // 8
    constexpr int STRIPS = PH / SR;            // 2
    constexpr int Yd = 2 * SR + 2, Xd = W + 2; // 6, 10
    constexpr int THREADS = 128;
    constexpr int HALF = 64;

    extern __shared__ float E[];               // 16*6*7*10 = 6720 floats

    const int b   = blockIdx.x / STRIPS;
    const int s   = blockIdx.x % STRIPS;
    const int tid = threadIdx.x;

    expand_strip<C, H, W, SR, THREADS>(in + (size_t)b * C * H * W, E, s, tid);
    __syncthreads();

    const int px = tid % PW;
    const int pr = (tid / PW) % SR;
    const int og = (tid / (PW * SR)) % OG;
    const int cs = tid / (PW * SR * OG);

    float acc[OT][4];
#pragma unroll
    for (int o = 0; o < OT; o++) acc[o][0] = acc[o][1] = acc[o][2] = acc[o][3] = 0.0f;

    conv_body<8, OT, Yd, Xd>(E, Wg, acc, cs * 8, pr, px, og * OT * C, C);

    __syncthreads();                            // all conv reads of E done
    float* P = E;                               // reuse arena: 64*17 floats
    const int slot = tid % HALF;                // same (px,pr,og) across halves
    if (cs == 1) {
#pragma unroll
        for (int o = 0; o < OT; o++)
#pragma unroll
            for (int k = 0; k < 4; k++) P[slot * 17 + o * 4 + k] = acc[o][k];
    }
    __syncthreads();
    if (cs == 0) {
        float* outb = out + (size_t)b * O * PH * PW;
        const int prow = s * SR + pr;
#pragma unroll
        for (int o = 0; o < OT; o++) {
            float v0 = acc[o][0] + P[slot * 17 + o * 4 + 0];
            float v1 = acc[o][1] + P[slot * 17 + o * 4 + 1];
            float v2 = acc[o][2] + P[slot * 17 + o * 4 + 2];
            float v3 = acc[o][3] + P[slot * 17 + o * 4 + 3];
            float m = fmaxf(fmaxf(v0, v1), fmaxf(v2, v3));
            outb[((og * OT + o) * PH + prow) * PW + px] = m;
        }
    }
}

// ---------------- final linear 512 -> 100 (direct linw rows, float4) ----------------
__global__ void __launch_bounds__(128) linear_k(const float* __restrict__ hbase,
                                                const float* __restrict__ linw,
                                                const float* __restrict__ bias,
                                                float* __restrict__ out) {
    __shared__ float hs[512];
    int b = blockIdx.x;
    for (int i = threadIdx.x; i < 512; i += 128) hs[i] = hbase[(size_t)b * 512 + i];
    __syncthreads();
    int j = threadIdx.x;
    if (j < 100) {
        float a = __ldg(&bias[j]);
        const float4* wr = reinterpret_cast<const float4*>(linw + (size_t)j * 512);
        const float4* h4 = reinterpret_cast<const float4*>(hs);
#pragma unroll 8
        for (int f = 0; f < 128; f++) {
            float4 w = __ldg(&wr[f]);
            float4 hv = h4[f];
            a += w.x * hv.x + w.y * hv.y + w.z * hv.z + w.w * hv.w;
        }
        out[(size_t)b * 100 + j] = a;
    }
}

// ---------------- launch: two independent 128-image chains on two streams ----------------
extern "C" void kernel_launch(void* const* d_in, const int* in_sizes, int n_in,
                              void* d_out, int out_size) {
    const float* x     = (const float*)d_in[0];
    const float* c1bw  = (const float*)d_in[1];
    const float* c1sw  = (const float*)d_in[2];
    const float* c1sc  = (const float*)d_in[3];
    const float* c2bw  = (const float*)d_in[4];
    const float* c2sw  = (const float*)d_in[5];
    const float* c2sc  = (const float*)d_in[6];
    const float* c3bw  = (const float*)d_in[7];
    const float* c3sw  = (const float*)d_in[8];
    const float* c3sc  = (const float*)d_in[9];
    const float* linw  = (const float*)d_in[10];
    const float* linb  = (const float*)d_in[11];
    float* out = (float*)d_out;

    static float *p_W1, *p_W2, *p_W3, *p_o1, *p_o2, *p_o3;
    static cudaStream_t s1;
    static cudaEvent_t ev_fork, ev_join;
    static bool init = false;
    if (!init) {
        cudaGetSymbolAddress((void**)&p_W1, g_W1);
        cudaGetSymbolAddress((void**)&p_W2, g_W2);
        cudaGetSymbolAddress((void**)&p_W3, g_W3);
        cudaGetSymbolAddress((void**)&p_o1, g_out1);
        cudaGetSymbolAddress((void**)&p_o2, g_out2);
        cudaGetSymbolAddress((void**)&p_o3, g_out3);
        cudaStreamCreateWithFlags(&s1, cudaStreamNonBlocking);
        cudaEventCreateWithFlags(&ev_fork, cudaEventDisableTiming);
        cudaEventCreateWithFlags(&ev_join, cudaEventDisableTiming);
        init = true;
    }

    prep_all<<<(NPREP + 255) / 256, 256>>>(c1bw, c1sw, c1sc, c2bw, c2sw, c2sc,
                                           c3bw, c3sw, c3sc);

    // fork: chain B (second half of batch) runs on s1 after prep
    cudaEventRecord(ev_fork, 0);
    cudaStreamWaitEvent(s1, ev_fork, 0);

    const int SM1 = 3 * 6 * 7 * 34 * 4;   // 17136 B
    const int SM2 = 8 * 6 * 7 * 18 * 4;   // 24192 B
    const int SM3 = 16 * 6 * 7 * 10 * 4;  // 26880 B

    // ---- chain A: images [0, 128) on default stream ----
    kan_layer<3, 32, 32, 8, 4, 2><<<HALFB * 8, 64, SM1>>>(x, p_o1, p_W1);
    kan_layer<8, 16, 16, 16, 4, 2><<<HALFB * 4, 64, SM2>>>(p_o1, p_o2, p_W2);
    kan_layer3<<<HALFB * 2, 128, SM3>>>(p_o2, p_o3, p_W3);
    linear_k<<<HALFB, 128>>>(p_o3, linw, linb, out);

    // ---- chain B: images [128, 256) on s1 ----
    const float* xB  = x + (size_t)HALFB * 3 * 32 * 32;
    float* o1B = p_o1 + (size_t)HALFB * 8 * 16 * 16;
    float* o2B = p_o2 + (size_t)HALFB * 16 * 8 * 8;
    float* o3B = p_o3 + (size_t)HALFB * 32 * 4 * 4;
    kan_layer<3, 32, 32, 8, 4, 2><<<HALFB * 8, 64, SM1, s1>>>(xB, o1B, p_W1);
    kan_layer<8, 16, 16, 16, 4, 2><<<HALFB * 4, 64, SM2, s1>>>(o1B, o2B, p_W2);
    kan_layer3<<<HALFB * 2, 128, SM3, s1>>>(o2B, o3B, p_W3);
    linear_k<<<HALFB, 128, 0, s1>>>(o3B, linw, linb, out + (size_t)HALFB * 100);

    // join: default stream waits for chain B
    cudaEventRecord(ev_join, s1);
    cudaStreamWaitEvent(0, ev_join, 0);
}